// round 1
// baseline (speedup 1.0000x reference)
#include <cuda_runtime.h>
#include <cuda_bf16.h>
#include <cstdint>

// Problem shape: pred (N=8, V=3, C=24, T=8, H=128, W=128) fp32
// mask (N, H, W) int32 in {0,1}; vq_0 (1, C) fp32. Output: scalar fp32.
//
// num = sum |pred - vq0[c]| * (1 - mask[n,h,w])
// den = sum(1 - mask) * (V*C*T)

#define NTOT   8
#define VTOT   3
#define CTOT   24
#define TTOT   8
#define HW     16384              // 128*128
#define HW4    4096               // HW/4
#define THW4   32768              // T*HW/4  (elements of float4 per (n,v,c))
#define NPLANE4 2359296           // V*C*T*HW/4 (float4 per n)
#define TOTAL4 18874368           // N*V*C*T*HW/4
#define MASK4  32768              // N*HW/4
#define VCT    576                // V*C*T

__device__ double g_num;
__device__ int    g_cnt;

__global__ void init_kernel() {
    g_num = 0.0;
    g_cnt = 0;
}

// Count mask==0 over (N,H,W), vectorized int4.
__global__ void mask_count_kernel(const int4* __restrict__ mask) {
    int i = blockIdx.x * blockDim.x + threadIdx.x;
    int stride = gridDim.x * blockDim.x;
    int cnt = 0;
    for (; i < MASK4; i += stride) {
        int4 m = mask[i];
        cnt += (m.x == 0) + (m.y == 0) + (m.z == 0) + (m.w == 0);
    }
    // warp reduce
    #pragma unroll
    for (int off = 16; off; off >>= 1)
        cnt += __shfl_xor_sync(0xFFFFFFFFu, cnt, off);
    __shared__ int warp_part[8];
    int lane = threadIdx.x & 31, wid = threadIdx.x >> 5;
    if (lane == 0) warp_part[wid] = cnt;
    __syncthreads();
    if (wid == 0) {
        int v = (lane < (blockDim.x >> 5)) ? warp_part[lane] : 0;
        #pragma unroll
        for (int off = 4; off; off >>= 1)
            v += __shfl_xor_sync(0xFFFFFFFFu, v, off);
        if (lane == 0) atomicAdd(&g_cnt, v);
    }
}

__device__ __forceinline__ float group_contrib(float4 p, int4 m, float v) {
    float a = 0.f;
    if (m.x == 0) a += fabsf(p.x - v);
    if (m.y == 0) a += fabsf(p.y - v);
    if (m.z == 0) a += fabsf(p.z - v);
    if (m.w == 0) a += fabsf(p.w - v);
    return a;
}

__global__ void __launch_bounds__(256)
reduce_kernel(const float4* __restrict__ pred,
              const int4*   __restrict__ mask,
              const float*  __restrict__ vq0) {
    unsigned stride = gridDim.x * blockDim.x;
    unsigned base = blockIdx.x * blockDim.x + threadIdx.x;
    float acc = 0.f;

    // 4-way unrolled grid-stride: 4 pred float4 + 4 mask int4 in flight.
    unsigned i = base;
    for (; i + 3u * stride < TOTAL4; i += 4u * stride) {
        unsigned i0 = i, i1 = i + stride, i2 = i + 2u * stride, i3 = i + 3u * stride;
        float4 p0 = pred[i0], p1 = pred[i1], p2 = pred[i2], p3 = pred[i3];

        unsigned hw0 = i0 & (HW4 - 1), hw1 = i1 & (HW4 - 1);
        unsigned hw2 = i2 & (HW4 - 1), hw3 = i3 & (HW4 - 1);
        unsigned n0 = i0 / NPLANE4, n1 = i1 / NPLANE4;
        unsigned n2 = i2 / NPLANE4, n3 = i3 / NPLANE4;
        int4 m0 = mask[n0 * HW4 + hw0];
        int4 m1 = mask[n1 * HW4 + hw1];
        int4 m2 = mask[n2 * HW4 + hw2];
        int4 m3 = mask[n3 * HW4 + hw3];

        float v0 = __ldg(&vq0[(i0 >> 15) % CTOT]);
        float v1 = __ldg(&vq0[(i1 >> 15) % CTOT]);
        float v2 = __ldg(&vq0[(i2 >> 15) % CTOT]);
        float v3 = __ldg(&vq0[(i3 >> 15) % CTOT]);

        acc += group_contrib(p0, m0, v0);
        acc += group_contrib(p1, m1, v1);
        acc += group_contrib(p2, m2, v2);
        acc += group_contrib(p3, m3, v3);
    }
    // tail
    for (; i < TOTAL4; i += stride) {
        float4 p = pred[i];
        unsigned hw = i & (HW4 - 1);
        unsigned n  = i / NPLANE4;
        int4 m = mask[n * HW4 + hw];
        float v = __ldg(&vq0[(i >> 15) % CTOT]);
        acc += group_contrib(p, m, v);
    }

    // block reduce
    #pragma unroll
    for (int off = 16; off; off >>= 1)
        acc += __shfl_xor_sync(0xFFFFFFFFu, acc, off);
    __shared__ float warp_part[8];
    int lane = threadIdx.x & 31, wid = threadIdx.x >> 5;
    if (lane == 0) warp_part[wid] = acc;
    __syncthreads();
    if (wid == 0) {
        float v = (lane < 8) ? warp_part[lane] : 0.f;
        #pragma unroll
        for (int off = 4; off; off >>= 1)
            v += __shfl_xor_sync(0xFFFFFFFFu, v, off);
        if (lane == 0) atomicAdd(&g_num, (double)v);
    }
}

__global__ void finalize_kernel(float* __restrict__ out) {
    double den = (double)g_cnt * (double)VCT;
    out[0] = (float)(g_num / den);
}

extern "C" void kernel_launch(void* const* d_in, const int* in_sizes, int n_in,
                              void* d_out, int out_size) {
    const float4* pred = (const float4*)d_in[0];
    const int4*   mask = (const int4*)d_in[1];
    const float*  vq0  = (const float*)d_in[2];
    float* out = (float*)d_out;

    init_kernel<<<1, 1>>>();
    mask_count_kernel<<<64, 256>>>(mask);
    reduce_kernel<<<2368, 256>>>(pred, mask, vq0);
    finalize_kernel<<<1, 1>>>(out);
}

// round 3
// speedup vs baseline: 1.0747x; 1.0747x over previous
#include <cuda_runtime.h>
#include <cuda_bf16.h>
#include <cstdint>

// pred (N=8, V=3, C=24, T=8, H=128, W=128) fp32; mask (N,H,W) i32 {0,1};
// vq_0 (1,C) fp32. out = sum(|pred - vq0[c]| * (1-mask)) / (sum(1-mask)*V*C*T)
//
// Single fused kernel. Thread layout: tid = chunk*32768 + n*4096 + hw4,
// chunk in [0,18) selects 32 of the 576 (v,c,t) slices. Mask int4 loaded ONCE
// per thread and reused for all 32 pred groups -> mask LTS traffic ~9MB
// instead of 302MB. Last block finalizes and resets globals for graph replay.

#define CTOT    24
#define TTOT    8
#define HW4     4096              // 128*128/4
#define NPLANE4 2359296           // V*C*T*HW/4
#define VCT     576
#define NCHUNK  18                // 576/32
#define VCT_PER 32
#define NBLOCKS 2304              // 18*8*4096 / 256

__device__ double       g_num;
__device__ unsigned long long g_cnt;
__device__ unsigned     g_ticket;

__global__ void __launch_bounds__(256)
fused_kernel(const float4* __restrict__ pred,
             const int4*   __restrict__ mask,
             const float*  __restrict__ vq0,
             float*        __restrict__ out) {
    __shared__ float vqtab[VCT];
    for (int i = threadIdx.x; i < VCT; i += 256) {
        int c = (i >> 3) % CTOT;          // vct = (v*C + c)*T + t
        vqtab[i] = vq0[c];
    }
    __syncthreads();

    unsigned tid   = blockIdx.x * 256u + threadIdx.x;
    unsigned hw4   = tid & (HW4 - 1);
    unsigned n     = (tid >> 12) & 7u;
    unsigned chunk = tid >> 15;           // 0..17
    unsigned nhw   = tid & 32767u;        // n*HW4 + hw4

    int4 m = mask[nhw];
    float wx = (m.x == 0) ? 1.f : 0.f;
    float wy = (m.y == 0) ? 1.f : 0.f;
    float wz = (m.z == 0) ? 1.f : 0.f;
    float ww = (m.w == 0) ? 1.f : 0.f;
    unsigned nz = (unsigned)((m.x == 0) + (m.y == 0) + (m.z == 0) + (m.w == 0));
    unsigned long long cnt = (unsigned long long)nz * VCT_PER;

    const float4* p = pred + (size_t)n * NPLANE4 + (size_t)(chunk * VCT_PER) * HW4 + hw4;
    const float*  vt = vqtab + chunk * VCT_PER;

    float acc = 0.f;
    #pragma unroll 16
    for (int j = 0; j < VCT_PER; j++) {
        float4 q = p[(size_t)j * HW4];
        float v = vt[j];
        acc = fmaf(fabsf(q.x - v), wx, acc);
        acc = fmaf(fabsf(q.y - v), wy, acc);
        acc = fmaf(fabsf(q.z - v), wz, acc);
        acc = fmaf(fabsf(q.w - v), ww, acc);
    }

    // block reduce (float sum + count only from lane-uniform nz, so count can
    // be reduced by warp 0 math: every thread in warp contributes)
    #pragma unroll
    for (int off = 16; off; off >>= 1) {
        acc += __shfl_xor_sync(0xFFFFFFFFu, acc, off);
        cnt += __shfl_xor_sync(0xFFFFFFFFu, cnt, off);
    }
    __shared__ float  warp_sum[8];
    __shared__ unsigned long long warp_cnt[8];
    int lane = threadIdx.x & 31, wid = threadIdx.x >> 5;
    if (lane == 0) { warp_sum[wid] = acc; warp_cnt[wid] = cnt; }
    __syncthreads();

    __shared__ bool is_last;
    if (threadIdx.x == 0) {
        float s = 0.f;
        unsigned long long k = 0;
        #pragma unroll
        for (int w = 0; w < 8; w++) { s += warp_sum[w]; k += warp_cnt[w]; }
        atomicAdd(&g_num, (double)s);
        atomicAdd(&g_cnt, k);
        __threadfence();
        unsigned t = atomicInc(&g_ticket, NBLOCKS - 1);
        is_last = (t == NBLOCKS - 1);
    }
    __syncthreads();

    if (is_last && threadIdx.x == 0) {
        __threadfence();
        double num = *((volatile double*)&g_num);
        unsigned long long den = *((volatile unsigned long long*)&g_cnt);
        out[0] = (float)(num / (double)den);
        // reset for next graph replay (atomicInc already wrapped g_ticket to 0)
        g_num = 0.0;
        g_cnt = 0ull;
        __threadfence();
    }
}

extern "C" void kernel_launch(void* const* d_in, const int* in_sizes, int n_in,
                              void* d_out, int out_size) {
    const float4* pred = (const float4*)d_in[0];
    const int4*   mask = (const int4*)d_in[1];
    const float*  vq0  = (const float*)d_in[2];
    float* out = (float*)d_out;

    fused_kernel<<<NBLOCKS, 256>>>(pred, mask, vq0, out);
}

// round 4
// speedup vs baseline: 1.1135x; 1.0361x over previous
#include <cuda_runtime.h>
#include <cuda_bf16.h>
#include <cstdint>

// pred (N=8, V=3, C=24, T=8, H=128, W=128) fp32; mask (N,H,W) i32 {0,1};
// vq_0 (1,C) fp32. out = sum(|pred - vq0[c]| * (1-mask)) / (sum(1-mask)*V*C*T)
//
// Persistent single-wave grid (148 SMs x 8 blocks) with dynamic tile stealing:
// 9216 tiles, each tile = 256 threads x 8 pred float4 (stride HW4) sharing one
// mask int4 per thread. Dynamic scheduling absorbs the between-SM L2-die
// variance (spr~1.10) that a static mapping pays. Last block finalizes and
// resets all globals so the kernel is graph-replay deterministic.

#define CTOT    24
#define HW4     4096              // 128*128/4
#define NPLANE4 2359296           // V*C*T*HW/4
#define VCT     576
#define JPER    8                 // (v,c,t) slices per tile
#define NTILES  9216              // 576/8 * 8(n) * 4096(hw4) / 256(threads)
#define NBLOCKS 1184              // 148 SMs * 8

__device__ double              g_num;
__device__ unsigned long long  g_cnt;
__device__ unsigned            g_work;
__device__ unsigned            g_ticket;

__global__ void __launch_bounds__(256)
fused_kernel(const float4* __restrict__ pred,
             const int4*   __restrict__ mask,
             const float*  __restrict__ vq0,
             float*        __restrict__ out) {
    __shared__ float vqtab[VCT];
    for (int i = threadIdx.x; i < VCT; i += 256) {
        int c = (i >> 3) % CTOT;          // vct = (v*C + c)*T + t
        vqtab[i] = vq0[c];
    }

    __shared__ unsigned cur_tile;
    float acc = 0.f;
    unsigned long long cnt = 0ull;

    for (;;) {
        __syncthreads();                  // protect cur_tile reuse (also covers vqtab init)
        if (threadIdx.x == 0)
            cur_tile = atomicAdd(&g_work, 1u);
        __syncthreads();
        unsigned t = cur_tile;
        if (t >= NTILES) break;

        unsigned tid   = t * 256u + threadIdx.x;
        unsigned hw4   = tid & (HW4 - 1);
        unsigned n     = (tid >> 12) & 7u;
        unsigned chunk = tid >> 15;       // 0..71
        unsigned nhw   = tid & 32767u;

        int4 m = mask[nhw];
        float wx = (m.x == 0) ? 1.f : 0.f;
        float wy = (m.y == 0) ? 1.f : 0.f;
        float wz = (m.z == 0) ? 1.f : 0.f;
        float ww = (m.w == 0) ? 1.f : 0.f;
        cnt += (unsigned long long)((m.x == 0) + (m.y == 0) + (m.z == 0) + (m.w == 0)) * JPER;

        const float4* p  = pred + (size_t)n * NPLANE4 + (size_t)(chunk * JPER) * HW4 + hw4;
        const float*  vt = vqtab + chunk * JPER;

        #pragma unroll
        for (int j = 0; j < JPER; j++) {
            float4 q = p[(size_t)j * HW4];
            float v = vt[j];
            acc = fmaf(fabsf(q.x - v), wx, acc);
            acc = fmaf(fabsf(q.y - v), wy, acc);
            acc = fmaf(fabsf(q.z - v), wz, acc);
            acc = fmaf(fabsf(q.w - v), ww, acc);
        }
    }

    // block reduce
    #pragma unroll
    for (int off = 16; off; off >>= 1) {
        acc += __shfl_xor_sync(0xFFFFFFFFu, acc, off);
        cnt += __shfl_xor_sync(0xFFFFFFFFu, cnt, off);
    }
    __shared__ float              warp_sum[8];
    __shared__ unsigned long long warp_cnt[8];
    int lane = threadIdx.x & 31, wid = threadIdx.x >> 5;
    if (lane == 0) { warp_sum[wid] = acc; warp_cnt[wid] = cnt; }
    __syncthreads();

    __shared__ bool is_last;
    if (threadIdx.x == 0) {
        float s = 0.f;
        unsigned long long k = 0ull;
        #pragma unroll
        for (int w = 0; w < 8; w++) { s += warp_sum[w]; k += warp_cnt[w]; }
        atomicAdd(&g_num, (double)s);
        atomicAdd(&g_cnt, k);
        __threadfence();
        unsigned tk = atomicInc(&g_ticket, NBLOCKS - 1);
        is_last = (tk == NBLOCKS - 1);
    }
    __syncthreads();

    if (is_last && threadIdx.x == 0) {
        __threadfence();
        double num = *((volatile double*)&g_num);
        unsigned long long den = *((volatile unsigned long long*)&g_cnt);
        out[0] = (float)(num / (double)den);
        // reset for next graph replay (g_ticket already wrapped to 0)
        g_num  = 0.0;
        g_cnt  = 0ull;
        g_work = 0u;
        __threadfence();
    }
}

extern "C" void kernel_launch(void* const* d_in, const int* in_sizes, int n_in,
                              void* d_out, int out_size) {
    const float4* pred = (const float4*)d_in[0];
    const int4*   mask = (const int4*)d_in[1];
    const float*  vq0  = (const float*)d_in[2];
    float* out = (float*)d_out;

    fused_kernel<<<NBLOCKS, 256>>>(pred, mask, vq0, out);
}